// round 1
// baseline (speedup 1.0000x reference)
#include <cuda_runtime.h>

// ---------------------------------------------------------------------------
// SubMLP: 4 layers. Algebraic simplification:
//   BN_p(y) = a_p*y + c_p,  a_p = g*rsqrt(v+eps), c_p = beta - m*a
//   Layer1: branch s = BN_s(W_s x)           -> stacked GEMM (3072x512), scaled W
//   Layer2-4: branch s = sum_p BN_p(W_p x_s) -> single W_eff = sum_p a_p.W_p
// Branches folded into M (plane-major [s][b][k]) -> one GEMM per layer.
// Gating: mask = (sum_s h[b,o,s] > 0), applied elementwise.
// Full fp32 (gate sign test forbids tf32/bf16). Inner loop uses fma.rn.f32x2.
// ---------------------------------------------------------------------------

#define EPSBN 1e-5f

#define N_B   8192
#define IN_F  512
#define H1D   1024
#define H2D   2048

// -------------------- scratch (device globals; no allocations) -------------
__device__ float g_h1 [N_B * 3 * H1D];       // layer1 out, [b][s*1024+o]
__device__ float g_h1g[3 * N_B * H1D];       // gated, plane-major [s][b][o]
__device__ float g_h2 [3 * N_B * H2D];       // plane-major
__device__ float g_h3 [3 * N_B * H1D];       // plane-major
__device__ float g_w1s[3 * H1D * IN_F];      // scaled stacked W1
__device__ float g_w2e[H2D * H1D];
__device__ float g_w3e[H1D * H2D];
__device__ float g_w4e[IN_F * H1D];
__device__ float g_c1[3 * H1D];
__device__ float g_c2[H2D];
__device__ float g_c3[H1D];
__device__ float g_c4[IN_F];

// -------------------- f32x2 helpers ----------------------------------------
__device__ __forceinline__ unsigned long long pack2(float lo, float hi) {
    unsigned long long r;
    asm("mov.b64 %0, {%1, %2};" : "=l"(r) : "f"(lo), "f"(hi));
    return r;
}
__device__ __forceinline__ void fma2(unsigned long long& d, unsigned long long a,
                                     unsigned long long b) {
    asm("fma.rn.f32x2 %0, %1, %2, %0;" : "+l"(d) : "l"(a), "l"(b));
}
__device__ __forceinline__ float2 unpack2(unsigned long long v) {
    float2 f;
    asm("mov.b64 {%0, %1}, %2;" : "=f"(f.x), "=f"(f.y) : "l"(v));
    return f;
}

// -------------------- weight prep ------------------------------------------
__device__ __forceinline__ float bn_scale(float g, float v) {
    float vv = v + EPSBN;
    float a = rsqrtf(vv);
    a = a * (1.5f - 0.5f * vv * a * a);   // Newton refine
    return g * a;
}

__global__ void prep_w1_kernel(const float* __restrict__ W, const float* __restrict__ g,
                               const float* __restrict__ be, const float* __restrict__ m,
                               const float* __restrict__ v, float* __restrict__ Ws,
                               float* __restrict__ bias) {
    int i = blockIdx.x * blockDim.x + threadIdx.x;
    if (i >= 3 * H1D * IN_F) return;
    int row = i >> 9;  // /512
    float a = bn_scale(g[row], v[row]);
    Ws[i] = W[i] * a;
    if ((i & (IN_F - 1)) == 0) bias[row] = be[row] - m[row] * a;
}

__global__ void prep_we_kernel(const float* __restrict__ W, const float* __restrict__ g,
                               const float* __restrict__ be, const float* __restrict__ m,
                               const float* __restrict__ v, float* __restrict__ We,
                               float* __restrict__ bias, int Cout, int K) {
    int i = blockIdx.x * blockDim.x + threadIdx.x;
    if (i >= Cout * K) return;
    int o = i / K;
    int k = i - o * K;
    float acc = 0.f;
#pragma unroll
    for (int s = 0; s < 3; s++) {
        float a = bn_scale(g[s * Cout + o], v[s * Cout + o]);
        acc += a * W[(s * Cout + o) * K + k];
    }
    We[i] = acc;
    if (k == 0) {
        float cb = 0.f;
#pragma unroll
        for (int s = 0; s < 3; s++) {
            float a = bn_scale(g[s * Cout + o], v[s * Cout + o]);
            cb += be[s * Cout + o] - m[s * Cout + o] * a;
        }
        bias[o] = cb;
    }
}

// -------------------- GEMM: C[M,N] = A[M,K] * W[N,K]^T + bias[N] -----------
// BM=BN=128, BK=16, 256 threads, 8x8 per thread, f32x2 inner, double-buffered.
// INTERLEAVE=1: row r = s*8192 + b, write C to out[b*(N*3) + n*3 + s].
#define BM 128
#define BN 128
#define BK 16

template <int INTERLEAVE>
__global__ void __launch_bounds__(256) gemm_f32(const float* __restrict__ A,
                                                const float* __restrict__ W,
                                                const float* __restrict__ bias,
                                                float* __restrict__ C, int M, int N,
                                                int K) {
    __shared__ __align__(16) float As[2][BK][BM];
    __shared__ __align__(16) float Bs[2][BK][BN];

    const int tid = threadIdx.x;
    const int m0 = blockIdx.y * BM;
    const int n0 = blockIdx.x * BN;

    // loader mapping: 2 float4 per operand per thread
    const int lr = tid >> 2;          // 0..63
    const int lk = (tid & 3) << 2;    // 0,4,8,12
    const float* Aptr = A + (long)(m0 + lr) * K + lk;
    const float* Wptr = W + (long)(n0 + lr) * K + lk;
    const long strideA = 64L * K;

    // compute mapping
    const int tx = tid & 15;
    const int ty = tid >> 4;
    const int cr = ty * 4;   // rows cr..cr+3, cr+64..cr+67
    const int cc = tx * 4;   // cols cc..cc+3, cc+64..cc+67

    unsigned long long acc[8][4];
#pragma unroll
    for (int i = 0; i < 8; i++)
#pragma unroll
        for (int j = 0; j < 4; j++) acc[i][j] = 0ULL;

    const int nk = K / BK;

    float4 ra0 = *(const float4*)(Aptr);
    float4 ra1 = *(const float4*)(Aptr + strideA);
    float4 rb0 = *(const float4*)(Wptr);
    float4 rb1 = *(const float4*)(Wptr + strideA);

#define STORE_TILES(nb)                                                                 \
    do {                                                                                \
        As[nb][lk + 0][lr] = ra0.x; As[nb][lk + 1][lr] = ra0.y;                         \
        As[nb][lk + 2][lr] = ra0.z; As[nb][lk + 3][lr] = ra0.w;                         \
        As[nb][lk + 0][lr + 64] = ra1.x; As[nb][lk + 1][lr + 64] = ra1.y;               \
        As[nb][lk + 2][lr + 64] = ra1.z; As[nb][lk + 3][lr + 64] = ra1.w;               \
        Bs[nb][lk + 0][lr] = rb0.x; Bs[nb][lk + 1][lr] = rb0.y;                         \
        Bs[nb][lk + 2][lr] = rb0.z; Bs[nb][lk + 3][lr] = rb0.w;                         \
        Bs[nb][lk + 0][lr + 64] = rb1.x; Bs[nb][lk + 1][lr + 64] = rb1.y;               \
        Bs[nb][lk + 2][lr + 64] = rb1.z; Bs[nb][lk + 3][lr + 64] = rb1.w;               \
    } while (0)

    STORE_TILES(0);
    __syncthreads();

    int buf = 0;
    for (int kt = 0; kt < nk; ++kt) {
        if (kt + 1 < nk) {
            const float* Ap = Aptr + (kt + 1) * BK;
            const float* Wp = Wptr + (kt + 1) * BK;
            ra0 = *(const float4*)(Ap);
            ra1 = *(const float4*)(Ap + strideA);
            rb0 = *(const float4*)(Wp);
            rb1 = *(const float4*)(Wp + strideA);
        }
#pragma unroll
        for (int k = 0; k < BK; ++k) {
            float4 a0 = *(const float4*)&As[buf][k][cr];
            float4 a1 = *(const float4*)&As[buf][k][cr + 64];
            ulonglong2 b0 = *(const ulonglong2*)&Bs[buf][k][cc];
            ulonglong2 b1 = *(const ulonglong2*)&Bs[buf][k][cc + 64];
            unsigned long long ap[8];
            ap[0] = pack2(a0.x, a0.x); ap[1] = pack2(a0.y, a0.y);
            ap[2] = pack2(a0.z, a0.z); ap[3] = pack2(a0.w, a0.w);
            ap[4] = pack2(a1.x, a1.x); ap[5] = pack2(a1.y, a1.y);
            ap[6] = pack2(a1.z, a1.z); ap[7] = pack2(a1.w, a1.w);
#pragma unroll
            for (int i = 0; i < 8; i++) {
                fma2(acc[i][0], ap[i], b0.x);
                fma2(acc[i][1], ap[i], b0.y);
                fma2(acc[i][2], ap[i], b1.x);
                fma2(acc[i][3], ap[i], b1.y);
            }
        }
        if (kt + 1 < nk) STORE_TILES(buf ^ 1);
        __syncthreads();
        buf ^= 1;
    }

    // -------------------- epilogue --------------------
    float4 bi0 = *(const float4*)(bias + n0 + cc);
    float4 bi1 = *(const float4*)(bias + n0 + cc + 64);

#pragma unroll
    for (int i = 0; i < 8; i++) {
        int rlocal = (i < 4) ? (cr + i) : (64 + cr + i - 4);
        int row = m0 + rlocal;
        float2 p0 = unpack2(acc[i][0]);
        float2 p1 = unpack2(acc[i][1]);
        float2 p2 = unpack2(acc[i][2]);
        float2 p3 = unpack2(acc[i][3]);
        float4 o0 = make_float4(p0.x + bi0.x, p0.y + bi0.y, p1.x + bi0.z, p1.y + bi0.w);
        float4 o1 = make_float4(p2.x + bi1.x, p2.y + bi1.y, p3.x + bi1.z, p3.y + bi1.w);
        if (!INTERLEAVE) {
            *(float4*)&C[(long)row * N + n0 + cc] = o0;
            *(float4*)&C[(long)row * N + n0 + cc + 64] = o1;
        } else {
            int s = row >> 13;       // /8192
            int b = row & 8191;
            long base = (long)b * (N * 3) + s;
            C[base + (long)(n0 + cc + 0) * 3] = o0.x;
            C[base + (long)(n0 + cc + 1) * 3] = o0.y;
            C[base + (long)(n0 + cc + 2) * 3] = o0.z;
            C[base + (long)(n0 + cc + 3) * 3] = o0.w;
            C[base + (long)(n0 + cc + 64) * 3] = o1.x;
            C[base + (long)(n0 + cc + 65) * 3] = o1.y;
            C[base + (long)(n0 + cc + 66) * 3] = o1.z;
            C[base + (long)(n0 + cc + 67) * 3] = o1.w;
        }
    }
}

// -------------------- gating ------------------------------------------------
__device__ __forceinline__ float4 gmul(float4 v, float4 m) {
    return make_float4(v.x * m.x, v.y * m.y, v.z * m.z, v.w * m.w);
}

// layer1: h1 [b][s*1024+o] -> gated plane-major h1g [s][b][o]
__global__ void gate1_kernel(const float4* __restrict__ h1, float4* __restrict__ h1g) {
    int i = blockIdx.x * blockDim.x + threadIdx.x;
    if (i >= N_B * (H1D / 4)) return;
    int b = i >> 8;          // /256
    int o4 = i & 255;
    const float4* row = h1 + (long)b * (3 * H1D / 4);
    float4 v0 = row[o4];
    float4 v1 = row[256 + o4];
    float4 v2 = row[512 + o4];
    float4 m;
    m.x = (v0.x + v1.x + v2.x > 0.f) ? 1.f : 0.f;
    m.y = (v0.y + v1.y + v2.y > 0.f) ? 1.f : 0.f;
    m.z = (v0.z + v1.z + v2.z > 0.f) ? 1.f : 0.f;
    m.w = (v0.w + v1.w + v2.w > 0.f) ? 1.f : 0.f;
    long p = (long)N_B * (H1D / 4);
    h1g[0 * p + i] = gmul(v0, m);
    h1g[1 * p + i] = gmul(v1, m);
    h1g[2 * p + i] = gmul(v2, m);
}

// in-place gate on plane-major h [3][8192][Nc]
__global__ void gate_ip_kernel(float4* __restrict__ h, int plane4) {
    int i = blockIdx.x * blockDim.x + threadIdx.x;
    if (i >= plane4) return;
    float4 v0 = h[i];
    float4 v1 = h[i + plane4];
    float4 v2 = h[i + 2L * plane4];
    float4 m;
    m.x = (v0.x + v1.x + v2.x > 0.f) ? 1.f : 0.f;
    m.y = (v0.y + v1.y + v2.y > 0.f) ? 1.f : 0.f;
    m.z = (v0.z + v1.z + v2.z > 0.f) ? 1.f : 0.f;
    m.w = (v0.w + v1.w + v2.w > 0.f) ? 1.f : 0.f;
    h[i] = gmul(v0, m);
    h[i + plane4] = gmul(v1, m);
    h[i + 2L * plane4] = gmul(v2, m);
}

// -------------------- launch ------------------------------------------------
extern "C" void kernel_launch(void* const* d_in, const int* in_sizes, int n_in,
                              void* d_out, int out_size) {
    const float* x  = (const float*)d_in[0];
    const float* W1 = (const float*)d_in[1];
    const float* G1 = (const float*)d_in[2];
    const float* B1 = (const float*)d_in[3];
    const float* M1 = (const float*)d_in[4];
    const float* V1 = (const float*)d_in[5];
    const float* W2 = (const float*)d_in[6];
    const float* G2 = (const float*)d_in[7];
    const float* B2 = (const float*)d_in[8];
    const float* M2 = (const float*)d_in[9];
    const float* V2 = (const float*)d_in[10];
    const float* W3 = (const float*)d_in[11];
    const float* G3 = (const float*)d_in[12];
    const float* B3 = (const float*)d_in[13];
    const float* M3 = (const float*)d_in[14];
    const float* V3 = (const float*)d_in[15];
    const float* W4 = (const float*)d_in[16];
    const float* G4 = (const float*)d_in[17];
    const float* B4 = (const float*)d_in[18];
    const float* M4 = (const float*)d_in[19];
    const float* V4 = (const float*)d_in[20];
    float* out = (float*)d_out;

    float *h1, *h1g, *h2, *h3, *w1s, *w2e, *w3e, *w4e, *c1, *c2, *c3, *c4;
    cudaGetSymbolAddress((void**)&h1, g_h1);
    cudaGetSymbolAddress((void**)&h1g, g_h1g);
    cudaGetSymbolAddress((void**)&h2, g_h2);
    cudaGetSymbolAddress((void**)&h3, g_h3);
    cudaGetSymbolAddress((void**)&w1s, g_w1s);
    cudaGetSymbolAddress((void**)&w2e, g_w2e);
    cudaGetSymbolAddress((void**)&w3e, g_w3e);
    cudaGetSymbolAddress((void**)&w4e, g_w4e);
    cudaGetSymbolAddress((void**)&c1, g_c1);
    cudaGetSymbolAddress((void**)&c2, g_c2);
    cudaGetSymbolAddress((void**)&c3, g_c3);
    cudaGetSymbolAddress((void**)&c4, g_c4);

    const int T = 256;
    // weight prep
    prep_w1_kernel<<<(3 * H1D * IN_F + T - 1) / T, T>>>(W1, G1, B1, M1, V1, w1s, c1);
    prep_we_kernel<<<(H2D * H1D + T - 1) / T, T>>>(W2, G2, B2, M2, V2, w2e, c2, H2D, H1D);
    prep_we_kernel<<<(H1D * H2D + T - 1) / T, T>>>(W3, G3, B3, M3, V3, w3e, c3, H1D, H2D);
    prep_we_kernel<<<(IN_F * H1D + T - 1) / T, T>>>(W4, G4, B4, M4, V4, w4e, c4, IN_F, H1D);

    dim3 blk(256);
    // layer 1: [8192,512] x [3072,512]^T -> h1 [8192,3072]
    gemm_f32<0><<<dim3(3 * H1D / BN, N_B / BM), blk>>>(x, w1s, c1, h1, N_B, 3 * H1D, IN_F);
    gate1_kernel<<<(N_B * (H1D / 4) + T - 1) / T, T>>>((const float4*)h1, (float4*)h1g);
    // layer 2: [24576,1024] x [2048,1024]^T
    gemm_f32<0><<<dim3(H2D / BN, 3 * N_B / BM), blk>>>(h1g, w2e, c2, h2, 3 * N_B, H2D, H1D);
    gate_ip_kernel<<<(N_B * H2D / 4 + T - 1) / T, T>>>((float4*)h2, N_B * H2D / 4);
    // layer 3: [24576,2048] x [1024,2048]^T
    gemm_f32<0><<<dim3(H1D / BN, 3 * N_B / BM), blk>>>(h2, w3e, c3, h3, 3 * N_B, H1D, H2D);
    gate_ip_kernel<<<(N_B * H1D / 4 + T - 1) / T, T>>>((float4*)h3, N_B * H1D / 4);
    // layer 4: [24576,1024] x [512,1024]^T -> interleaved out [b][o][s]
    gemm_f32<1><<<dim3(IN_F / BN, 3 * N_B / BM), blk>>>(h3, w4e, c4, out, 3 * N_B, IN_F, H1D);
}

// round 2
// speedup vs baseline: 1.0005x; 1.0005x over previous
#include <cuda_runtime.h>

// ---------------------------------------------------------------------------
// SubMLP: 4 layers. Algebraic simplification:
//   BN_p(y) = a_p*y + c_p,  a_p = g*rsqrt(v+eps), c_p = beta - m*a
//   Layer1: branch s = BN_s(W_s x)           -> stacked GEMM (3072x512), scaled W
//   Layer2-4: branch s = sum_p BN_p(W_p x_s) -> single W_eff = sum_p a_p.W_p
// Branches folded into M (plane-major [s][b][k]) -> one GEMM per layer.
// Gating: mask = (sum_s h[b,o,s] > 0), applied elementwise.
// Full fp32 (gate sign test forbids tf32/bf16). Inner loop uses fma.rn.f32x2.
// ---------------------------------------------------------------------------

#define EPSBN 1e-5f

#define N_B   8192
#define IN_F  512
#define H1D   1024
#define H2D   2048

// -------------------- scratch (device globals; no allocations) -------------
__device__ float g_h1 [N_B * 3 * H1D];       // layer1 out, [b][s*1024+o]
__device__ float g_h1g[3 * N_B * H1D];       // gated, plane-major [s][b][o]
__device__ float g_h2 [3 * N_B * H2D];       // plane-major
__device__ float g_h3 [3 * N_B * H1D];       // plane-major
__device__ float g_w1s[3 * H1D * IN_F];      // scaled stacked W1
__device__ float g_w2e[H2D * H1D];
__device__ float g_w3e[H1D * H2D];
__device__ float g_w4e[IN_F * H1D];
__device__ float g_c1[3 * H1D];
__device__ float g_c2[H2D];
__device__ float g_c3[H1D];
__device__ float g_c4[IN_F];

// -------------------- f32x2 helpers ----------------------------------------
__device__ __forceinline__ unsigned long long pack2(float lo, float hi) {
    unsigned long long r;
    asm("mov.b64 %0, {%1, %2};" : "=l"(r) : "f"(lo), "f"(hi));
    return r;
}
__device__ __forceinline__ void fma2(unsigned long long& d, unsigned long long a,
                                     unsigned long long b) {
    asm("fma.rn.f32x2 %0, %1, %2, %0;" : "+l"(d) : "l"(a), "l"(b));
}
__device__ __forceinline__ float2 unpack2(unsigned long long v) {
    float2 f;
    asm("mov.b64 {%0, %1}, %2;" : "=f"(f.x), "=f"(f.y) : "l"(v));
    return f;
}

// -------------------- weight prep ------------------------------------------
__device__ __forceinline__ float bn_scale(float g, float v) {
    float vv = v + EPSBN;
    float a = rsqrtf(vv);
    a = a * (1.5f - 0.5f * vv * a * a);   // Newton refine
    return g * a;
}

__global__ void prep_w1_kernel(const float* __restrict__ W, const float* __restrict__ g,
                               const float* __restrict__ be, const float* __restrict__ m,
                               const float* __restrict__ v, float* __restrict__ Ws,
                               float* __restrict__ bias) {
    int i = blockIdx.x * blockDim.x + threadIdx.x;
    if (i >= 3 * H1D * IN_F) return;
    int row = i >> 9;  // /512
    float a = bn_scale(g[row], v[row]);
    Ws[i] = W[i] * a;
    if ((i & (IN_F - 1)) == 0) bias[row] = be[row] - m[row] * a;
}

__global__ void prep_we_kernel(const float* __restrict__ W, const float* __restrict__ g,
                               const float* __restrict__ be, const float* __restrict__ m,
                               const float* __restrict__ v, float* __restrict__ We,
                               float* __restrict__ bias, int Cout, int K) {
    int i = blockIdx.x * blockDim.x + threadIdx.x;
    if (i >= Cout * K) return;
    int o = i / K;
    int k = i - o * K;
    float acc = 0.f;
#pragma unroll
    for (int s = 0; s < 3; s++) {
        float a = bn_scale(g[s * Cout + o], v[s * Cout + o]);
        acc += a * W[(s * Cout + o) * K + k];
    }
    We[i] = acc;
    if (k == 0) {
        float cb = 0.f;
#pragma unroll
        for (int s = 0; s < 3; s++) {
            float a = bn_scale(g[s * Cout + o], v[s * Cout + o]);
            cb += be[s * Cout + o] - m[s * Cout + o] * a;
        }
        bias[o] = cb;
    }
}

// -------------------- GEMM: C[M,N] = A[M,K] * W[N,K]^T + bias[N] -----------
// BM=BN=128, BK=16, 256 threads, 8x8 per thread, f32x2 inner, double-buffered.
// INTERLEAVE=1: row r = s*8192 + b, write C to out[b*(N*3) + n*3 + s].
#define BM 128
#define BN 128
#define BK 16

template <int INTERLEAVE>
__global__ void __launch_bounds__(256) gemm_f32(const float* __restrict__ A,
                                                const float* __restrict__ W,
                                                const float* __restrict__ bias,
                                                float* __restrict__ C, int M, int N,
                                                int K) {
    __shared__ __align__(16) float As[2][BK][BM];
    __shared__ __align__(16) float Bs[2][BK][BN];

    const int tid = threadIdx.x;
    const int m0 = blockIdx.y * BM;
    const int n0 = blockIdx.x * BN;

    // loader mapping: 2 float4 per operand per thread
    const int lr = tid >> 2;          // 0..63
    const int lk = (tid & 3) << 2;    // 0,4,8,12
    const float* Aptr = A + (long)(m0 + lr) * K + lk;
    const float* Wptr = W + (long)(n0 + lr) * K + lk;
    const long strideA = 64L * K;

    // compute mapping
    const int tx = tid & 15;
    const int ty = tid >> 4;
    const int cr = ty * 4;   // rows cr..cr+3, cr+64..cr+67
    const int cc = tx * 4;   // cols cc..cc+3, cc+64..cc+67

    unsigned long long acc[8][4];
#pragma unroll
    for (int i = 0; i < 8; i++)
#pragma unroll
        for (int j = 0; j < 4; j++) acc[i][j] = 0ULL;

    const int nk = K / BK;

    float4 ra0 = *(const float4*)(Aptr);
    float4 ra1 = *(const float4*)(Aptr + strideA);
    float4 rb0 = *(const float4*)(Wptr);
    float4 rb1 = *(const float4*)(Wptr + strideA);

#define STORE_TILES(nb)                                                                 \
    do {                                                                                \
        As[nb][lk + 0][lr] = ra0.x; As[nb][lk + 1][lr] = ra0.y;                         \
        As[nb][lk + 2][lr] = ra0.z; As[nb][lk + 3][lr] = ra0.w;                         \
        As[nb][lk + 0][lr + 64] = ra1.x; As[nb][lk + 1][lr + 64] = ra1.y;               \
        As[nb][lk + 2][lr + 64] = ra1.z; As[nb][lk + 3][lr + 64] = ra1.w;               \
        Bs[nb][lk + 0][lr] = rb0.x; Bs[nb][lk + 1][lr] = rb0.y;                         \
        Bs[nb][lk + 2][lr] = rb0.z; Bs[nb][lk + 3][lr] = rb0.w;                         \
        Bs[nb][lk + 0][lr + 64] = rb1.x; Bs[nb][lk + 1][lr + 64] = rb1.y;               \
        Bs[nb][lk + 2][lr + 64] = rb1.z; Bs[nb][lk + 3][lr + 64] = rb1.w;               \
    } while (0)

    STORE_TILES(0);
    __syncthreads();

    int buf = 0;
    for (int kt = 0; kt < nk; ++kt) {
        if (kt + 1 < nk) {
            const float* Ap = Aptr + (kt + 1) * BK;
            const float* Wp = Wptr + (kt + 1) * BK;
            ra0 = *(const float4*)(Ap);
            ra1 = *(const float4*)(Ap + strideA);
            rb0 = *(const float4*)(Wp);
            rb1 = *(const float4*)(Wp + strideA);
        }
#pragma unroll
        for (int k = 0; k < BK; ++k) {
            float4 a0 = *(const float4*)&As[buf][k][cr];
            float4 a1 = *(const float4*)&As[buf][k][cr + 64];
            ulonglong2 b0 = *(const ulonglong2*)&Bs[buf][k][cc];
            ulonglong2 b1 = *(const ulonglong2*)&Bs[buf][k][cc + 64];
            unsigned long long ap[8];
            ap[0] = pack2(a0.x, a0.x); ap[1] = pack2(a0.y, a0.y);
            ap[2] = pack2(a0.z, a0.z); ap[3] = pack2(a0.w, a0.w);
            ap[4] = pack2(a1.x, a1.x); ap[5] = pack2(a1.y, a1.y);
            ap[6] = pack2(a1.z, a1.z); ap[7] = pack2(a1.w, a1.w);
#pragma unroll
            for (int i = 0; i < 8; i++) {
                fma2(acc[i][0], ap[i], b0.x);
                fma2(acc[i][1], ap[i], b0.y);
                fma2(acc[i][2], ap[i], b1.x);
                fma2(acc[i][3], ap[i], b1.y);
            }
        }
        if (kt + 1 < nk) STORE_TILES(buf ^ 1);
        __syncthreads();
        buf ^= 1;
    }

    // -------------------- epilogue --------------------
    float4 bi0 = *(const float4*)(bias + n0 + cc);
    float4 bi1 = *(const float4*)(bias + n0 + cc + 64);

#pragma unroll
    for (int i = 0; i < 8; i++) {
        int rlocal = (i < 4) ? (cr + i) : (64 + cr + i - 4);
        int row = m0 + rlocal;
        float2 p0 = unpack2(acc[i][0]);
        float2 p1 = unpack2(acc[i][1]);
        float2 p2 = unpack2(acc[i][2]);
        float2 p3 = unpack2(acc[i][3]);
        float4 o0 = make_float4(p0.x + bi0.x, p0.y + bi0.y, p1.x + bi0.z, p1.y + bi0.w);
        float4 o1 = make_float4(p2.x + bi1.x, p2.y + bi1.y, p3.x + bi1.z, p3.y + bi1.w);
        if (!INTERLEAVE) {
            *(float4*)&C[(long)row * N + n0 + cc] = o0;
            *(float4*)&C[(long)row * N + n0 + cc + 64] = o1;
        } else {
            int s = row >> 13;       // /8192
            int b = row & 8191;
            long base = (long)b * (N * 3) + s;
            C[base + (long)(n0 + cc + 0) * 3] = o0.x;
            C[base + (long)(n0 + cc + 1) * 3] = o0.y;
            C[base + (long)(n0 + cc + 2) * 3] = o0.z;
            C[base + (long)(n0 + cc + 3) * 3] = o0.w;
            C[base + (long)(n0 + cc + 64) * 3] = o1.x;
            C[base + (long)(n0 + cc + 65) * 3] = o1.y;
            C[base + (long)(n0 + cc + 66) * 3] = o1.z;
            C[base + (long)(n0 + cc + 67) * 3] = o1.w;
        }
    }
}

// -------------------- gating ------------------------------------------------
__device__ __forceinline__ float4 gmul(float4 v, float4 m) {
    return make_float4(v.x * m.x, v.y * m.y, v.z * m.z, v.w * m.w);
}

// layer1: h1 [b][s*1024+o] -> gated plane-major h1g [s][b][o]
__global__ void gate1_kernel(const float4* __restrict__ h1, float4* __restrict__ h1g) {
    int i = blockIdx.x * blockDim.x + threadIdx.x;
    if (i >= N_B * (H1D / 4)) return;
    int b = i >> 8;          // /256
    int o4 = i & 255;
    const float4* row = h1 + (long)b * (3 * H1D / 4);
    float4 v0 = row[o4];
    float4 v1 = row[256 + o4];
    float4 v2 = row[512 + o4];
    float4 m;
    m.x = (v0.x + v1.x + v2.x > 0.f) ? 1.f : 0.f;
    m.y = (v0.y + v1.y + v2.y > 0.f) ? 1.f : 0.f;
    m.z = (v0.z + v1.z + v2.z > 0.f) ? 1.f : 0.f;
    m.w = (v0.w + v1.w + v2.w > 0.f) ? 1.f : 0.f;
    long p = (long)N_B * (H1D / 4);
    h1g[0 * p + i] = gmul(v0, m);
    h1g[1 * p + i] = gmul(v1, m);
    h1g[2 * p + i] = gmul(v2, m);
}

// in-place gate on plane-major h [3][8192][Nc]
__global__ void gate_ip_kernel(float4* __restrict__ h, int plane4) {
    int i = blockIdx.x * blockDim.x + threadIdx.x;
    if (i >= plane4) return;
    float4 v0 = h[i];
    float4 v1 = h[i + plane4];
    float4 v2 = h[i + 2L * plane4];
    float4 m;
    m.x = (v0.x + v1.x + v2.x > 0.f) ? 1.f : 0.f;
    m.y = (v0.y + v1.y + v2.y > 0.f) ? 1.f : 0.f;
    m.z = (v0.z + v1.z + v2.z > 0.f) ? 1.f : 0.f;
    m.w = (v0.w + v1.w + v2.w > 0.f) ? 1.f : 0.f;
    h[i] = gmul(v0, m);
    h[i + plane4] = gmul(v1, m);
    h[i + 2L * plane4] = gmul(v2, m);
}

// -------------------- launch ------------------------------------------------
extern "C" void kernel_launch(void* const* d_in, const int* in_sizes, int n_in,
                              void* d_out, int out_size) {
    const float* x  = (const float*)d_in[0];
    const float* W1 = (const float*)d_in[1];
    const float* G1 = (const float*)d_in[2];
    const float* B1 = (const float*)d_in[3];
    const float* M1 = (const float*)d_in[4];
    const float* V1 = (const float*)d_in[5];
    const float* W2 = (const float*)d_in[6];
    const float* G2 = (const float*)d_in[7];
    const float* B2 = (const float*)d_in[8];
    const float* M2 = (const float*)d_in[9];
    const float* V2 = (const float*)d_in[10];
    const float* W3 = (const float*)d_in[11];
    const float* G3 = (const float*)d_in[12];
    const float* B3 = (const float*)d_in[13];
    const float* M3 = (const float*)d_in[14];
    const float* V3 = (const float*)d_in[15];
    const float* W4 = (const float*)d_in[16];
    const float* G4 = (const float*)d_in[17];
    const float* B4 = (const float*)d_in[18];
    const float* M4 = (const float*)d_in[19];
    const float* V4 = (const float*)d_in[20];
    float* out = (float*)d_out;

    float *h1, *h1g, *h2, *h3, *w1s, *w2e, *w3e, *w4e, *c1, *c2, *c3, *c4;
    cudaGetSymbolAddress((void**)&h1, g_h1);
    cudaGetSymbolAddress((void**)&h1g, g_h1g);
    cudaGetSymbolAddress((void**)&h2, g_h2);
    cudaGetSymbolAddress((void**)&h3, g_h3);
    cudaGetSymbolAddress((void**)&w1s, g_w1s);
    cudaGetSymbolAddress((void**)&w2e, g_w2e);
    cudaGetSymbolAddress((void**)&w3e, g_w3e);
    cudaGetSymbolAddress((void**)&w4e, g_w4e);
    cudaGetSymbolAddress((void**)&c1, g_c1);
    cudaGetSymbolAddress((void**)&c2, g_c2);
    cudaGetSymbolAddress((void**)&c3, g_c3);
    cudaGetSymbolAddress((void**)&c4, g_c4);

    const int T = 256;
    // weight prep
    prep_w1_kernel<<<(3 * H1D * IN_F + T - 1) / T, T>>>(W1, G1, B1, M1, V1, w1s, c1);
    prep_we_kernel<<<(H2D * H1D + T - 1) / T, T>>>(W2, G2, B2, M2, V2, w2e, c2, H2D, H1D);
    prep_we_kernel<<<(H1D * H2D + T - 1) / T, T>>>(W3, G3, B3, M3, V3, w3e, c3, H1D, H2D);
    prep_we_kernel<<<(IN_F * H1D + T - 1) / T, T>>>(W4, G4, B4, M4, V4, w4e, c4, IN_F, H1D);

    dim3 blk(256);
    // layer 1: [8192,512] x [3072,512]^T -> h1 [8192,3072]
    gemm_f32<0><<<dim3(3 * H1D / BN, N_B / BM), blk>>>(x, w1s, c1, h1, N_B, 3 * H1D, IN_F);
    gate1_kernel<<<(N_B * (H1D / 4) + T - 1) / T, T>>>((const float4*)h1, (float4*)h1g);
    // layer 2: [24576,1024] x [2048,1024]^T
    gemm_f32<0><<<dim3(H2D / BN, 3 * N_B / BM), blk>>>(h1g, w2e, c2, h2, 3 * N_B, H2D, H1D);
    gate_ip_kernel<<<(N_B * H2D / 4 + T - 1) / T, T>>>((float4*)h2, N_B * H2D / 4);
    // layer 3: [24576,2048] x [1024,2048]^T
    gemm_f32<0><<<dim3(H1D / BN, 3 * N_B / BM), blk>>>(h2, w3e, c3, h3, 3 * N_B, H1D, H2D);
    gate_ip_kernel<<<(N_B * H1D / 4 + T - 1) / T, T>>>((float4*)h3, N_B * H1D / 4);
    // layer 4: [24576,1024] x [512,1024]^T -> interleaved out [b][o][s]
    gemm_f32<1><<<dim3(IN_F / BN, 3 * N_B / BM), blk>>>(h3, w4e, c4, out, 3 * N_B, IN_F, H1D);
}

// round 3
// speedup vs baseline: 1.0009x; 1.0004x over previous
#include <cuda_runtime.h>

// ---------------------------------------------------------------------------
// SubMLP: 4 layers. Algebraic simplification:
//   BN_p(y) = a_p*y + c_p,  a_p = g*rsqrt(v+eps), c_p = beta - m*a
//   Layer1: branch s = BN_s(W_s x)           -> stacked GEMM (3072x512), scaled W
//   Layer2-4: branch s = sum_p BN_p(W_p x_s) -> single W_eff = sum_p a_p.W_p
// Branches folded into M (plane-major [s][b][k]) -> one GEMM per layer.
// Gating: mask = (sum_s h[b,o,s] > 0), applied elementwise.
// Full fp32 (gate sign test forbids tf32/bf16). Inner loop uses fma.rn.f32x2.
// ---------------------------------------------------------------------------

#define EPSBN 1e-5f

#define N_B   8192
#define IN_F  512
#define H1D   1024
#define H2D   2048

// -------------------- scratch (device globals; no allocations) -------------
__device__ float g_h1 [N_B * 3 * H1D];       // layer1 out, [b][s*1024+o]
__device__ float g_h1g[3 * N_B * H1D];       // gated, plane-major [s][b][o]
__device__ float g_h2 [3 * N_B * H2D];       // plane-major
__device__ float g_h3 [3 * N_B * H1D];       // plane-major
__device__ float g_w1s[3 * H1D * IN_F];      // scaled stacked W1
__device__ float g_w2e[H2D * H1D];
__device__ float g_w3e[H1D * H2D];
__device__ float g_w4e[IN_F * H1D];
__device__ float g_c1[3 * H1D];
__device__ float g_c2[H2D];
__device__ float g_c3[H1D];
__device__ float g_c4[IN_F];

// -------------------- f32x2 helpers ----------------------------------------
__device__ __forceinline__ unsigned long long pack2(float lo, float hi) {
    unsigned long long r;
    asm("mov.b64 %0, {%1, %2};" : "=l"(r) : "f"(lo), "f"(hi));
    return r;
}
__device__ __forceinline__ void fma2(unsigned long long& d, unsigned long long a,
                                     unsigned long long b) {
    asm("fma.rn.f32x2 %0, %1, %2, %0;" : "+l"(d) : "l"(a), "l"(b));
}
__device__ __forceinline__ float2 unpack2(unsigned long long v) {
    float2 f;
    asm("mov.b64 {%0, %1}, %2;" : "=f"(f.x), "=f"(f.y) : "l"(v));
    return f;
}

// -------------------- weight prep ------------------------------------------
__device__ __forceinline__ float bn_scale(float g, float v) {
    float vv = v + EPSBN;
    float a = rsqrtf(vv);
    a = a * (1.5f - 0.5f * vv * a * a);   // Newton refine
    return g * a;
}

__global__ void prep_w1_kernel(const float* __restrict__ W, const float* __restrict__ g,
                               const float* __restrict__ be, const float* __restrict__ m,
                               const float* __restrict__ v, float* __restrict__ Ws,
                               float* __restrict__ bias) {
    int i = blockIdx.x * blockDim.x + threadIdx.x;
    if (i >= 3 * H1D * IN_F) return;
    int row = i >> 9;  // /512
    float a = bn_scale(g[row], v[row]);
    Ws[i] = W[i] * a;
    if ((i & (IN_F - 1)) == 0) bias[row] = be[row] - m[row] * a;
}

__global__ void prep_we_kernel(const float* __restrict__ W, const float* __restrict__ g,
                               const float* __restrict__ be, const float* __restrict__ m,
                               const float* __restrict__ v, float* __restrict__ We,
                               float* __restrict__ bias, int Cout, int K) {
    int i = blockIdx.x * blockDim.x + threadIdx.x;
    if (i >= Cout * K) return;
    int o = i / K;
    int k = i - o * K;
    float acc = 0.f;
#pragma unroll
    for (int s = 0; s < 3; s++) {
        float a = bn_scale(g[s * Cout + o], v[s * Cout + o]);
        acc += a * W[(s * Cout + o) * K + k];
    }
    We[i] = acc;
    if (k == 0) {
        float cb = 0.f;
#pragma unroll
        for (int s = 0; s < 3; s++) {
            float a = bn_scale(g[s * Cout + o], v[s * Cout + o]);
            cb += be[s * Cout + o] - m[s * Cout + o] * a;
        }
        bias[o] = cb;
    }
}

// -------------------- GEMM: C[M,N] = A[M,K] * W[N,K]^T + bias[N] -----------
// BM=BN=128, BK=16, 256 threads, 8x8 per thread, f32x2 inner, double-buffered.
// INTERLEAVE=1: row r = s*8192 + b, write C to out[b*(N*3) + n*3 + s].
#define BM 128
#define BN 128
#define BK 16

template <int INTERLEAVE>
__global__ void __launch_bounds__(256) gemm_f32(const float* __restrict__ A,
                                                const float* __restrict__ W,
                                                const float* __restrict__ bias,
                                                float* __restrict__ C, int M, int N,
                                                int K) {
    __shared__ __align__(16) float As[2][BK][BM];
    __shared__ __align__(16) float Bs[2][BK][BN];

    const int tid = threadIdx.x;
    const int m0 = blockIdx.y * BM;
    const int n0 = blockIdx.x * BN;

    // loader mapping: 2 float4 per operand per thread
    const int lr = tid >> 2;          // 0..63
    const int lk = (tid & 3) << 2;    // 0,4,8,12
    const float* Aptr = A + (long)(m0 + lr) * K + lk;
    const float* Wptr = W + (long)(n0 + lr) * K + lk;
    const long strideA = 64L * K;

    // compute mapping
    const int tx = tid & 15;
    const int ty = tid >> 4;
    const int cr = ty * 4;   // rows cr..cr+3, cr+64..cr+67
    const int cc = tx * 4;   // cols cc..cc+3, cc+64..cc+67

    unsigned long long acc[8][4];
#pragma unroll
    for (int i = 0; i < 8; i++)
#pragma unroll
        for (int j = 0; j < 4; j++) acc[i][j] = 0ULL;

    const int nk = K / BK;

    float4 ra0 = *(const float4*)(Aptr);
    float4 ra1 = *(const float4*)(Aptr + strideA);
    float4 rb0 = *(const float4*)(Wptr);
    float4 rb1 = *(const float4*)(Wptr + strideA);

#define STORE_TILES(nb)                                                                 \
    do {                                                                                \
        As[nb][lk + 0][lr] = ra0.x; As[nb][lk + 1][lr] = ra0.y;                         \
        As[nb][lk + 2][lr] = ra0.z; As[nb][lk + 3][lr] = ra0.w;                         \
        As[nb][lk + 0][lr + 64] = ra1.x; As[nb][lk + 1][lr + 64] = ra1.y;               \
        As[nb][lk + 2][lr + 64] = ra1.z; As[nb][lk + 3][lr + 64] = ra1.w;               \
        Bs[nb][lk + 0][lr] = rb0.x; Bs[nb][lk + 1][lr] = rb0.y;                         \
        Bs[nb][lk + 2][lr] = rb0.z; Bs[nb][lk + 3][lr] = rb0.w;                         \
        Bs[nb][lk + 0][lr + 64] = rb1.x; Bs[nb][lk + 1][lr + 64] = rb1.y;               \
        Bs[nb][lk + 2][lr + 64] = rb1.z; Bs[nb][lk + 3][lr + 64] = rb1.w;               \
    } while (0)

    STORE_TILES(0);
    __syncthreads();

    int buf = 0;
    for (int kt = 0; kt < nk; ++kt) {
        if (kt + 1 < nk) {
            const float* Ap = Aptr + (kt + 1) * BK;
            const float* Wp = Wptr + (kt + 1) * BK;
            ra0 = *(const float4*)(Ap);
            ra1 = *(const float4*)(Ap + strideA);
            rb0 = *(const float4*)(Wp);
            rb1 = *(const float4*)(Wp + strideA);
        }
#pragma unroll
        for (int k = 0; k < BK; ++k) {
            float4 a0 = *(const float4*)&As[buf][k][cr];
            float4 a1 = *(const float4*)&As[buf][k][cr + 64];
            ulonglong2 b0 = *(const ulonglong2*)&Bs[buf][k][cc];
            ulonglong2 b1 = *(const ulonglong2*)&Bs[buf][k][cc + 64];
            unsigned long long ap[8];
            ap[0] = pack2(a0.x, a0.x); ap[1] = pack2(a0.y, a0.y);
            ap[2] = pack2(a0.z, a0.z); ap[3] = pack2(a0.w, a0.w);
            ap[4] = pack2(a1.x, a1.x); ap[5] = pack2(a1.y, a1.y);
            ap[6] = pack2(a1.z, a1.z); ap[7] = pack2(a1.w, a1.w);
#pragma unroll
            for (int i = 0; i < 8; i++) {
                fma2(acc[i][0], ap[i], b0.x);
                fma2(acc[i][1], ap[i], b0.y);
                fma2(acc[i][2], ap[i], b1.x);
                fma2(acc[i][3], ap[i], b1.y);
            }
        }
        if (kt + 1 < nk) STORE_TILES(buf ^ 1);
        __syncthreads();
        buf ^= 1;
    }

    // -------------------- epilogue --------------------
    float4 bi0 = *(const float4*)(bias + n0 + cc);
    float4 bi1 = *(const float4*)(bias + n0 + cc + 64);

#pragma unroll
    for (int i = 0; i < 8; i++) {
        int rlocal = (i < 4) ? (cr + i) : (64 + cr + i - 4);
        int row = m0 + rlocal;
        float2 p0 = unpack2(acc[i][0]);
        float2 p1 = unpack2(acc[i][1]);
        float2 p2 = unpack2(acc[i][2]);
        float2 p3 = unpack2(acc[i][3]);
        float4 o0 = make_float4(p0.x + bi0.x, p0.y + bi0.y, p1.x + bi0.z, p1.y + bi0.w);
        float4 o1 = make_float4(p2.x + bi1.x, p2.y + bi1.y, p3.x + bi1.z, p3.y + bi1.w);
        if (!INTERLEAVE) {
            *(float4*)&C[(long)row * N + n0 + cc] = o0;
            *(float4*)&C[(long)row * N + n0 + cc + 64] = o1;
        } else {
            int s = row >> 13;       // /8192
            int b = row & 8191;
            long base = (long)b * (N * 3) + s;
            C[base + (long)(n0 + cc + 0) * 3] = o0.x;
            C[base + (long)(n0 + cc + 1) * 3] = o0.y;
            C[base + (long)(n0 + cc + 2) * 3] = o0.z;
            C[base + (long)(n0 + cc + 3) * 3] = o0.w;
            C[base + (long)(n0 + cc + 64) * 3] = o1.x;
            C[base + (long)(n0 + cc + 65) * 3] = o1.y;
            C[base + (long)(n0 + cc + 66) * 3] = o1.z;
            C[base + (long)(n0 + cc + 67) * 3] = o1.w;
        }
    }
}

// -------------------- gating ------------------------------------------------
__device__ __forceinline__ float4 gmul(float4 v, float4 m) {
    return make_float4(v.x * m.x, v.y * m.y, v.z * m.z, v.w * m.w);
}

// layer1: h1 [b][s*1024+o] -> gated plane-major h1g [s][b][o]
__global__ void gate1_kernel(const float4* __restrict__ h1, float4* __restrict__ h1g) {
    int i = blockIdx.x * blockDim.x + threadIdx.x;
    if (i >= N_B * (H1D / 4)) return;
    int b = i >> 8;          // /256
    int o4 = i & 255;
    const float4* row = h1 + (long)b * (3 * H1D / 4);
    float4 v0 = row[o4];
    float4 v1 = row[256 + o4];
    float4 v2 = row[512 + o4];
    float4 m;
    m.x = (v0.x + v1.x + v2.x > 0.f) ? 1.f : 0.f;
    m.y = (v0.y + v1.y + v2.y > 0.f) ? 1.f : 0.f;
    m.z = (v0.z + v1.z + v2.z > 0.f) ? 1.f : 0.f;
    m.w = (v0.w + v1.w + v2.w > 0.f) ? 1.f : 0.f;
    long p = (long)N_B * (H1D / 4);
    h1g[0 * p + i] = gmul(v0, m);
    h1g[1 * p + i] = gmul(v1, m);
    h1g[2 * p + i] = gmul(v2, m);
}

// in-place gate on plane-major h [3][8192][Nc]
__global__ void gate_ip_kernel(float4* __restrict__ h, int plane4) {
    int i = blockIdx.x * blockDim.x + threadIdx.x;
    if (i >= plane4) return;
    float4 v0 = h[i];
    float4 v1 = h[i + plane4];
    float4 v2 = h[i + 2L * plane4];
    float4 m;
    m.x = (v0.x + v1.x + v2.x > 0.f) ? 1.f : 0.f;
    m.y = (v0.y + v1.y + v2.y > 0.f) ? 1.f : 0.f;
    m.z = (v0.z + v1.z + v2.z > 0.f) ? 1.f : 0.f;
    m.w = (v0.w + v1.w + v2.w > 0.f) ? 1.f : 0.f;
    h[i] = gmul(v0, m);
    h[i + plane4] = gmul(v1, m);
    h[i + 2L * plane4] = gmul(v2, m);
}

// -------------------- launch ------------------------------------------------
extern "C" void kernel_launch(void* const* d_in, const int* in_sizes, int n_in,
                              void* d_out, int out_size) {
    const float* x  = (const float*)d_in[0];
    const float* W1 = (const float*)d_in[1];
    const float* G1 = (const float*)d_in[2];
    const float* B1 = (const float*)d_in[3];
    const float* M1 = (const float*)d_in[4];
    const float* V1 = (const float*)d_in[5];
    const float* W2 = (const float*)d_in[6];
    const float* G2 = (const float*)d_in[7];
    const float* B2 = (const float*)d_in[8];
    const float* M2 = (const float*)d_in[9];
    const float* V2 = (const float*)d_in[10];
    const float* W3 = (const float*)d_in[11];
    const float* G3 = (const float*)d_in[12];
    const float* B3 = (const float*)d_in[13];
    const float* M3 = (const float*)d_in[14];
    const float* V3 = (const float*)d_in[15];
    const float* W4 = (const float*)d_in[16];
    const float* G4 = (const float*)d_in[17];
    const float* B4 = (const float*)d_in[18];
    const float* M4 = (const float*)d_in[19];
    const float* V4 = (const float*)d_in[20];
    float* out = (float*)d_out;

    float *h1, *h1g, *h2, *h3, *w1s, *w2e, *w3e, *w4e, *c1, *c2, *c3, *c4;
    cudaGetSymbolAddress((void**)&h1, g_h1);
    cudaGetSymbolAddress((void**)&h1g, g_h1g);
    cudaGetSymbolAddress((void**)&h2, g_h2);
    cudaGetSymbolAddress((void**)&h3, g_h3);
    cudaGetSymbolAddress((void**)&w1s, g_w1s);
    cudaGetSymbolAddress((void**)&w2e, g_w2e);
    cudaGetSymbolAddress((void**)&w3e, g_w3e);
    cudaGetSymbolAddress((void**)&w4e, g_w4e);
    cudaGetSymbolAddress((void**)&c1, g_c1);
    cudaGetSymbolAddress((void**)&c2, g_c2);
    cudaGetSymbolAddress((void**)&c3, g_c3);
    cudaGetSymbolAddress((void**)&c4, g_c4);

    const int T = 256;
    // weight prep
    prep_w1_kernel<<<(3 * H1D * IN_F + T - 1) / T, T>>>(W1, G1, B1, M1, V1, w1s, c1);
    prep_we_kernel<<<(H2D * H1D + T - 1) / T, T>>>(W2, G2, B2, M2, V2, w2e, c2, H2D, H1D);
    prep_we_kernel<<<(H1D * H2D + T - 1) / T, T>>>(W3, G3, B3, M3, V3, w3e, c3, H1D, H2D);
    prep_we_kernel<<<(IN_F * H1D + T - 1) / T, T>>>(W4, G4, B4, M4, V4, w4e, c4, IN_F, H1D);

    dim3 blk(256);
    // layer 1: [8192,512] x [3072,512]^T -> h1 [8192,3072]
    gemm_f32<0><<<dim3(3 * H1D / BN, N_B / BM), blk>>>(x, w1s, c1, h1, N_B, 3 * H1D, IN_F);
    gate1_kernel<<<(N_B * (H1D / 4) + T - 1) / T, T>>>((const float4*)h1, (float4*)h1g);
    // layer 2: [24576,1024] x [2048,1024]^T
    gemm_f32<0><<<dim3(H2D / BN, 3 * N_B / BM), blk>>>(h1g, w2e, c2, h2, 3 * N_B, H2D, H1D);
    gate_ip_kernel<<<(N_B * H2D / 4 + T - 1) / T, T>>>((float4*)h2, N_B * H2D / 4);
    // layer 3: [24576,2048] x [1024,2048]^T
    gemm_f32<0><<<dim3(H1D / BN, 3 * N_B / BM), blk>>>(h2, w3e, c3, h3, 3 * N_B, H1D, H2D);
    gate_ip_kernel<<<(N_B * H1D / 4 + T - 1) / T, T>>>((float4*)h3, N_B * H1D / 4);
    // layer 4: [24576,1024] x [512,1024]^T -> interleaved out [b][o][s]
    gemm_f32<1><<<dim3(IN_F / BN, 3 * N_B / BM), blk>>>(h3, w4e, c4, out, 3 * N_B, IN_F, H1D);
}